// round 2
// baseline (speedup 1.0000x reference)
#include <cuda_runtime.h>

// SlowNorm: per-irrep L2 norms.
// irreps: (256,1) (256,3) (128,5) (64,7)  -> DIM=2112 in, OUT=704 out per row.
// Input offsets (floats): d1 [0,256), d3 [256,1024), d5 [1024,1664), d7 [1664,2112).
// Output offsets: [0,256) |x| ; [256,512) d=3 ; [512,640) d=5 ; [640,704) d=7.
//
// Persistent CTAs + cp.async double buffering: prefetch row i+G into buf[nxt]
// while computing row i from buf[cur], so DRAM reads never pause for compute.

#define DIM      2112
#define OUT_DIM  704
#define THREADS  256
#define GRID_BLOCKS 608   // 152 SMs * 4 CTAs

__device__ __forceinline__ void cp_async16(float* smem_dst, const float* gmem_src) {
    unsigned saddr = (unsigned)__cvta_generic_to_shared(smem_dst);
    asm volatile("cp.async.cg.shared.global [%0], [%1], 16;\n"
                 :: "r"(saddr), "l"(gmem_src));
}
__device__ __forceinline__ void cp_commit() {
    asm volatile("cp.async.commit_group;\n");
}
__device__ __forceinline__ void cp_wait1() {
    asm volatile("cp.async.wait_group 1;\n");
}
__device__ __forceinline__ void stcs(float* p, float v) {
    asm volatile("st.global.cs.f32 [%0], %1;\n" :: "l"(p), "f"(v));
}

__global__ __launch_bounds__(THREADS) void slownorm_kernel(
    const float* __restrict__ in, float* __restrict__ out, int batch)
{
    __shared__ float s[2][DIM];

    const int G = gridDim.x;
    long long row = blockIdx.x;
    if (row >= batch) return;

    // Prologue: stage first row into buffer 0.
    {
        const float* src = in + row * (long long)DIM;
        #pragma unroll
        for (int i = threadIdx.x; i < DIM / 4; i += THREADS)
            cp_async16(&s[0][i * 4], src + i * 4);
        cp_commit();
    }

    int cur = 0;
    for (; row < batch; row += G) {
        // Prefetch next row into the other buffer (safe: its compute finished
        // before the trailing __syncthreads of the previous iteration).
        const long long nrow = row + G;
        const int nxt = cur ^ 1;
        if (nrow < batch) {
            const float* src = in + nrow * (long long)DIM;
            #pragma unroll
            for (int i = threadIdx.x; i < DIM / 4; i += THREADS)
                cp_async16(&s[nxt][i * 4], src + i * 4);
        }
        cp_commit();            // always commit (possibly empty group) so
        cp_wait1();             // wait_group 1 guarantees buf[cur] complete
        __syncthreads();

        const float* __restrict__ b = s[cur];
        float* __restrict__ orow = out + row * (long long)OUT_DIM;

        #pragma unroll
        for (int o = threadIdx.x; o < OUT_DIM; o += THREADS) {
            float v;
            if (o < 256) {
                v = fabsf(b[o]);                       // d=1
            } else if (o < 512) {
                const int p = 256 + (o - 256) * 3;     // d=3
                float acc = b[p] * b[p];
                acc = fmaf(b[p + 1], b[p + 1], acc);
                acc = fmaf(b[p + 2], b[p + 2], acc);
                v = sqrtf(acc);
            } else if (o < 640) {
                const int p = 1024 + (o - 512) * 5;    // d=5
                float acc = b[p] * b[p];
                #pragma unroll
                for (int j = 1; j < 5; j++) acc = fmaf(b[p + j], b[p + j], acc);
                v = sqrtf(acc);
            } else {
                const int p = 1664 + (o - 640) * 7;    // d=7
                float acc = b[p] * b[p];
                #pragma unroll
                for (int j = 1; j < 7; j++) acc = fmaf(b[p + j], b[p + j], acc);
                v = sqrtf(acc);
            }
            stcs(orow + o, v);
        }
        __syncthreads();        // protect buf[cur] before it becomes prefetch dst
        cur = nxt;
    }
}

extern "C" void kernel_launch(void* const* d_in, const int* in_sizes, int n_in,
                              void* d_out, int out_size)
{
    const float* features = (const float*)d_in[0];
    float* out = (float*)d_out;
    const int batch = in_sizes[0] / DIM;   // 65536
    const int grid = batch < GRID_BLOCKS ? batch : GRID_BLOCKS;
    slownorm_kernel<<<grid, THREADS>>>(features, out, batch);
}

// round 3
// speedup vs baseline: 1.0384x; 1.0384x over previous
#include <cuda_runtime.h>

// SlowNorm: per-irrep L2 norms.
// irreps: (256,1) (256,3) (128,5) (64,7)  -> DIM=2112 in, OUT=704 out per row.
// Input offsets (floats): d1 [0,256), d3 [256,1024), d5 [1024,1664), d7 [1664,2112).
// Output offsets: [0,256) |x| ; [256,512) d=3 ; [512,640) d=5 ; [640,704) d=7.
//
// 2 adjacent rows per CTA (contiguous 16896B stage, high MLP), float4 smem
// compute, STG.128 vectorized output.

#define DIM      2112
#define OUT_DIM  704
#define THREADS  256
#define ROWS_PER_CTA 2
#define VEC_PER_ROW  (OUT_DIM / 4)          // 176
#define VEC_TOTAL    (ROWS_PER_CTA * VEC_PER_ROW)  // 352

__device__ __forceinline__ float4 ldcs4(const float4* p) {
    float4 v;
    asm volatile("ld.global.cs.v4.f32 {%0,%1,%2,%3}, [%4];\n"
                 : "=f"(v.x), "=f"(v.y), "=f"(v.z), "=f"(v.w) : "l"(p));
    return v;
}
__device__ __forceinline__ void stcs4(float4* p, float4 v) {
    asm volatile("st.global.cs.v4.f32 [%0], {%1,%2,%3,%4};\n"
                 :: "l"(p), "f"(v.x), "f"(v.y), "f"(v.z), "f"(v.w));
}

__global__ __launch_bounds__(THREADS) void slownorm_kernel(
    const float* __restrict__ in, float* __restrict__ out)
{
    __shared__ float s[ROWS_PER_CTA * DIM];   // 4224 floats = 16.5 KB

    const long long row0 = (long long)blockIdx.x * ROWS_PER_CTA;
    const float4* __restrict__ src =
        reinterpret_cast<const float4*>(in + row0 * DIM);
    float4* s4 = reinterpret_cast<float4*>(s);

    // Stage 2 contiguous rows: 1056 float4, ~4.1 per thread, fully coalesced.
    #pragma unroll
    for (int i = threadIdx.x; i < (ROWS_PER_CTA * DIM) / 4; i += THREADS)
        s4[i] = ldcs4(src + i);
    __syncthreads();

    float* __restrict__ obase = out + row0 * OUT_DIM;

    // 352 output float4-chunks over 256 threads (1-2 each).
    #pragma unroll
    for (int c = threadIdx.x; c < VEC_TOTAL; c += THREADS) {
        const int r = c / VEC_PER_ROW;          // 0 or 1
        const int q = c - r * VEC_PER_ROW;      // float4 index within row
        const float* __restrict__ b = s + r * DIM;
        float4 v;
        if (q < 64) {                           // d=1: |x|, outputs 4q..4q+3
            const float4 x = *reinterpret_cast<const float4*>(b + 4 * q);
            v.x = fabsf(x.x); v.y = fabsf(x.y);
            v.z = fabsf(x.z); v.w = fabsf(x.w);
        } else if (q < 128) {                   // d=3: base 256 + (o-256)*3
            const int p = 256 + (4 * q - 256) * 3;   // 12 floats
            float a[4];
            #pragma unroll
            for (int k = 0; k < 4; k++) {
                const float* e = b + p + 3 * k;
                float acc = e[0] * e[0];
                acc = fmaf(e[1], e[1], acc);
                acc = fmaf(e[2], e[2], acc);
                a[k] = sqrtf(acc);
            }
            v.x = a[0]; v.y = a[1]; v.z = a[2]; v.w = a[3];
        } else if (q < 160) {                   // d=5: base 1024 + (o-512)*5
            const int p = 1024 + (4 * q - 512) * 5;  // 20 floats
            float a[4];
            #pragma unroll
            for (int k = 0; k < 4; k++) {
                const float* e = b + p + 5 * k;
                float acc = e[0] * e[0];
                #pragma unroll
                for (int j = 1; j < 5; j++) acc = fmaf(e[j], e[j], acc);
                a[k] = sqrtf(acc);
            }
            v.x = a[0]; v.y = a[1]; v.z = a[2]; v.w = a[3];
        } else {                                // d=7: base 1664 + (o-640)*7
            const int p = 1664 + (4 * q - 640) * 7;  // 28 floats
            float a[4];
            #pragma unroll
            for (int k = 0; k < 4; k++) {
                const float* e = b + p + 7 * k;
                float acc = e[0] * e[0];
                #pragma unroll
                for (int j = 1; j < 7; j++) acc = fmaf(e[j], e[j], acc);
                a[k] = sqrtf(acc);
            }
            v.x = a[0]; v.y = a[1]; v.z = a[2]; v.w = a[3];
        }
        stcs4(reinterpret_cast<float4*>(obase + r * OUT_DIM + 4 * q), v);
    }
}

extern "C" void kernel_launch(void* const* d_in, const int* in_sizes, int n_in,
                              void* d_out, int out_size)
{
    const float* features = (const float*)d_in[0];
    float* out = (float*)d_out;
    const int batch = in_sizes[0] / DIM;       // 65536 (even)
    slownorm_kernel<<<batch / ROWS_PER_CTA, THREADS>>>(features, out);
}